// round 6
// baseline (speedup 1.0000x reference)
#include <cuda_runtime.h>
#include <cuda_bf16.h>
#include <stdint.h>

// Problem constants
#define BB 128
#define TT 256
#define CC 512
#define HH 2048
#define NCTA 64
// N_SUB = 3, DT = (1/255)/3 = 1/765
__device__ __constant__ float k_DT      = (float)(1.0/765.0);
__device__ __constant__ float k_HALF_DT = (float)(0.5/765.0);
__device__ __constant__ float k_SIXTH   = (float)(1.0/(765.0*6.0));

// ---------------- device-global scratch (no runtime allocation) ----------------
__device__ __align__(128) __nv_bfloat16 g_W1[CC*HH];   // [K=C][N=H]
__device__ __align__(128) __nv_bfloat16 g_W2[HH*HH];   // [K=H][N=H]
__device__ __align__(128) __nv_bfloat16 g_W3[HH*CC];   // [K=H][N=C]
__device__ __align__(128) __nv_bfloat16 g_a [BB*CC];   // bf16 MLP input
__device__ __align__(128) __nv_bfloat16 g_h1[BB*HH];
__device__ __align__(128) __nv_bfloat16 g_h2[BB*HH];
__device__ __align__(128) float g_y [BB*CC];           // fp32 ODE state
__device__ __align__(128) float g_ks[BB*CC];           // fp32 RK4 k-sum

// ---------------- grid barrier state ----------------
__device__ unsigned g_count;
__device__ volatile unsigned g_gen;

__device__ __forceinline__ void grid_barrier(unsigned &gen){
    __syncthreads();
    if (threadIdx.x == 0){
        __threadfence();                               // release prior writes
        if (atomicAdd(&g_count, 1u) == gridDim.x - 1u){
            atomicExch(&g_count, 0u);                  // reset for next barrier
            __threadfence();
            g_gen = gen + 1u;                          // release
        } else {
            while (g_gen == gen) { }                   // spin on L2
            __threadfence();                           // acquire
        }
    }
    __syncthreads();
    gen++;
}

// ---------------- small PTX helpers ----------------
__device__ __forceinline__ void cp16(void* s, const void* g){
    uint32_t sa = (uint32_t)__cvta_generic_to_shared(s);
    asm volatile("cp.async.cg.shared.global [%0], [%1], 16;\n" :: "r"(sa), "l"(g));
}
__device__ __forceinline__ void cpcommit(){ asm volatile("cp.async.commit_group;\n"); }
__device__ __forceinline__ void cpwait0(){ asm volatile("cp.async.wait_group 0;\n"); }
__device__ __forceinline__ void cpwait1(){ asm volatile("cp.async.wait_group 1;\n"); }

__device__ __forceinline__ void mma16816(float* c, const uint32_t* a, const uint32_t* b){
    asm volatile(
        "mma.sync.aligned.m16n8k16.row.col.f32.bf16.bf16.f32 "
        "{%0,%1,%2,%3},{%4,%5,%6,%7},{%8,%9},{%0,%1,%2,%3};\n"
        : "+f"(c[0]), "+f"(c[1]), "+f"(c[2]), "+f"(c[3])
        : "r"(a[0]), "r"(a[1]), "r"(a[2]), "r"(a[3]), "r"(b[0]), "r"(b[1]));
}

__device__ __forceinline__ uint32_t packbf(__nv_bfloat16 lo, __nv_bfloat16 hi){
    union { __nv_bfloat162 v; uint32_t u; } t;
    t.v.x = lo; t.v.y = hi; return t.u;
}

__device__ __forceinline__ float fast_tanh(float x){
    float y; asm("tanh.approx.f32 %0, %1;" : "=f"(y) : "f"(x)); return y;
}

// ---------------- generic GEMM tile (device function, runs inside persistent kernel) ----
// D[MT, NT] tile of A[MT, KDIM] @ W[KDIM, NN] at column nbase. A is pre-offset
// to the tile's first row. 8 warps in 4x2 (WM x WN). Epilogue gets
// (row0, col0, v[4]) covering rows {row0,row0+8} x cols {col0,col0+1} (local rows).
template<int MT, int NT, int KC, int KDIM, int NN, typename EPI>
__device__ __forceinline__ void gemm_tile(const __nv_bfloat16* __restrict__ A,
                                          const __nv_bfloat16* __restrict__ W,
                                          int nbase,
                                          __nv_bfloat16* __restrict__ As,
                                          __nv_bfloat16* __restrict__ Bs,
                                          EPI epi)
{
    constexpr int WM = 4, WN = 2;
    constexpr int MF = MT / (WM * 16);      // m16 fragments per warp
    constexpr int NF = NT / (WN * 8);       // n8 fragments per warp
    constexpr int SA = KC + 8;              // padded A smem row (bf16)
    constexpr int SB = NT + 8;              // padded B smem row (bf16)
    constexpr int NC = KDIM / KC;           // K chunks
    constexpr int SEGR = KC / 8;            // 16B segs per A row
    constexpr int ALOOP = MT * SEGR / 256;  // A-load tasks per thread
    constexpr int SEGB = NT / 8;            // 16B segs per B row
    constexpr int ASTR = MT * SA;           // smem stage stride (elems)
    constexpr int BSTR = KC * SB;

    const int tid  = threadIdx.x;
    const int lane = tid & 31;
    const int warp = tid >> 5;
    const int wm   = warp & 3;
    const int wn   = warp >> 2;
    const int g8   = lane >> 2;
    const int t4   = lane & 3;

    float acc[MF][NF][4];
    #pragma unroll
    for (int i = 0; i < MF; i++)
        #pragma unroll
        for (int j = 0; j < NF; j++)
            #pragma unroll
            for (int q = 0; q < 4; q++) acc[i][j][q] = 0.f;

    auto load = [&](int cidx, int st){
        const int kc = cidx * KC;
        #pragma unroll
        for (int i = 0; i < ALOOP; i++){
            int task = tid * ALOOP + i;
            int row = task / SEGR, seg = task % SEGR;
            cp16(&As[st * ASTR + row * SA + seg * 8], &A[row * KDIM + kc + seg * 8]);
        }
        if (tid < KC * SEGB){
            int row = tid / SEGB, seg = tid % SEGB;
            cp16(&Bs[st * BSTR + row * SB + seg * 8], &W[(kc + row) * NN + nbase + seg * 8]);
        }
        cpcommit();
    };

    load(0, 0);
    for (int c = 0; c < NC; c++){
        const int st = c & 1;
        if (c + 1 < NC){ load(c + 1, (c + 1) & 1); cpwait1(); }
        else           { cpwait0(); }
        __syncthreads();

        #pragma unroll
        for (int ks = 0; ks < KC / 16; ks++){
            const int k0 = ks * 16;
            uint32_t a[MF][4];
            #pragma unroll
            for (int mf = 0; mf < MF; mf++){
                int r0 = wm * (MF * 16) + mf * 16 + g8;
                const __nv_bfloat16* p0 = &As[st * ASTR + r0 * SA + k0 + t4 * 2];
                const __nv_bfloat16* p1 = &As[st * ASTR + (r0 + 8) * SA + k0 + t4 * 2];
                a[mf][0] = *reinterpret_cast<const uint32_t*>(p0);
                a[mf][1] = *reinterpret_cast<const uint32_t*>(p1);
                a[mf][2] = *reinterpret_cast<const uint32_t*>(p0 + 8);
                a[mf][3] = *reinterpret_cast<const uint32_t*>(p1 + 8);
            }
            uint32_t b[NF][2];
            #pragma unroll
            for (int nf = 0; nf < NF; nf++){
                int n0 = wn * (NF * 8) + nf * 8 + g8;
                int kr = k0 + t4 * 2;
                const __nv_bfloat16* bp = &Bs[st * BSTR];
                b[nf][0] = packbf(bp[kr * SB + n0],       bp[(kr + 1) * SB + n0]);
                b[nf][1] = packbf(bp[(kr + 8) * SB + n0], bp[(kr + 9) * SB + n0]);
            }
            #pragma unroll
            for (int mf = 0; mf < MF; mf++)
                #pragma unroll
                for (int nf = 0; nf < NF; nf++)
                    mma16816(acc[mf][nf], a[mf], b[nf]);
        }
        __syncthreads();
    }

    #pragma unroll
    for (int mf = 0; mf < MF; mf++)
        #pragma unroll
        for (int nf = 0; nf < NF; nf++){
            int r0 = wm * (MF * 16) + mf * 16 + g8;
            int gc = nbase + wn * (NF * 8) + nf * 8 + t4 * 2;
            epi(r0, gc, acc[mf][nf]);
        }
}

// ---------------- RK4 bookkeeping (layer-3 epilogue) ----------------
// stage 0: ksum = k1;           a = bf16(y + 0.5*dt*k)
// stage 1: ksum += 2*k2;        a = bf16(y + 0.5*dt*k)
// stage 2: ksum += 2*k3;        a = bf16(y + dt*k)
// stage 3: y += dt/6*(ksum+k4); a = bf16(y); optionally write out[:, t, :]
__device__ __forceinline__ void rk_ep(int r, int c, float k, int stage, int out_t,
                                      float* __restrict__ out)
{
    int idx = r * CC + c;
    if (stage == 3){
        float total = g_ks[idx] + k;
        float yn = fmaf(k_SIXTH, total, g_y[idx]);
        g_y[idx] = yn;
        g_a[idx] = __float2bfloat16(yn);
        if (out_t >= 0) out[r * TT * CC + out_t * CC + c] = yn;
    } else {
        float ks = (stage == 0) ? k : fmaf(2.f, k, g_ks[idx]);
        g_ks[idx] = ks;
        float al = (stage == 2) ? k_DT : k_HALF_DT;
        g_a[idx] = __float2bfloat16(fmaf(al, k, g_y[idx]));
    }
}

// ---------------- persistent kernel: entire time loop ----------------
__global__ void __launch_bounds__(256, 1)
ode_kernel(const float* __restrict__ b1,
           const float* __restrict__ b2,
           const float* __restrict__ b3,
           float* __restrict__ out)
{
    // Max smem across layer configs:
    //  L1/L2: As 2*128*40, Bs 2*32*40 ; L3: As 2*64*72, Bs 2*64*24
    __shared__ __align__(16) __nv_bfloat16 As[2 * 128 * 40];   // 20480 B
    __shared__ __align__(16) __nv_bfloat16 Bs[2 * 64 * 24];    //  6144 B

    const int cta = blockIdx.x;
    const int nb32 = cta * 32;                 // L1/L2 column base
    const int mb3  = (cta >> 5) * 64;          // L3 row base (0 or 64)
    const int nb3  = (cta & 31) * 16;          // L3 column base
    unsigned gen = 0;

    for (int t = 1; t < TT; t++){
        for (int sub = 0; sub < 3; sub++){     // N_SUB = 3
            for (int s = 0; s < 4; s++){       // RK4 stages
                // Layer 1: h1 = tanh(a @ W1 + b1)
                gemm_tile<128, 32, 32, CC, HH>(g_a, g_W1, nb32, As, Bs,
                    [&](int r, int gc, float* v){
                        float bb0 = b1[gc], bb1 = b1[gc + 1];
                        union { __nv_bfloat162 v2; uint32_t u; } x0, x1;
                        x0.v2.x = __float2bfloat16(fast_tanh(v[0] + bb0));
                        x0.v2.y = __float2bfloat16(fast_tanh(v[1] + bb1));
                        x1.v2.x = __float2bfloat16(fast_tanh(v[2] + bb0));
                        x1.v2.y = __float2bfloat16(fast_tanh(v[3] + bb1));
                        *reinterpret_cast<uint32_t*>(&g_h1[r * HH + gc])       = x0.u;
                        *reinterpret_cast<uint32_t*>(&g_h1[(r + 8) * HH + gc]) = x1.u;
                    });
                grid_barrier(gen);

                // Layer 2: h2 = tanh(h1 @ W2 + b2)
                gemm_tile<128, 32, 32, HH, HH>(g_h1, g_W2, nb32, As, Bs,
                    [&](int r, int gc, float* v){
                        float bb0 = b2[gc], bb1 = b2[gc + 1];
                        union { __nv_bfloat162 v2; uint32_t u; } x0, x1;
                        x0.v2.x = __float2bfloat16(fast_tanh(v[0] + bb0));
                        x0.v2.y = __float2bfloat16(fast_tanh(v[1] + bb1));
                        x1.v2.x = __float2bfloat16(fast_tanh(v[2] + bb0));
                        x1.v2.y = __float2bfloat16(fast_tanh(v[3] + bb1));
                        *reinterpret_cast<uint32_t*>(&g_h2[r * HH + gc])       = x0.u;
                        *reinterpret_cast<uint32_t*>(&g_h2[(r + 8) * HH + gc]) = x1.u;
                    });
                grid_barrier(gen);

                // Layer 3: k = h2 @ W3 + b3, fused RK4 update
                const int out_t = (s == 3 && sub == 2) ? t : -1;
                gemm_tile<64, 16, 64, HH, CC>(g_h2 + mb3 * HH, g_W3, nb3, As, Bs,
                    [&](int r, int gc, float* v){
                        float bb0 = b3[gc], bb1 = b3[gc + 1];
                        rk_ep(mb3 + r,     gc,     v[0] + bb0, s, out_t, out);
                        rk_ep(mb3 + r,     gc + 1, v[1] + bb1, s, out_t, out);
                        rk_ep(mb3 + r + 8, gc,     v[2] + bb0, s, out_t, out);
                        rk_ep(mb3 + r + 8, gc + 1, v[3] + bb1, s, out_t, out);
                    });
                grid_barrier(gen);
            }
        }
    }
}

// ---------------- prep: quantize weights, init state, write out[:,0,:] ----------------
__global__ void prep_kernel(const float* __restrict__ x,
                            const float* __restrict__ W1,
                            const float* __restrict__ W2,
                            const float* __restrict__ W3,
                            float* __restrict__ out)
{
    int idx = blockIdx.x * blockDim.x + threadIdx.x;
    if (idx == 0){ g_count = 0; g_gen = 0; }
    if (idx < CC * HH) g_W1[idx] = __float2bfloat16(W1[idx]);
    if (idx < HH * HH) g_W2[idx] = __float2bfloat16(W2[idx]);
    if (idx < HH * CC) g_W3[idx] = __float2bfloat16(W3[idx]);
    if (idx < BB * CC){
        int b = idx >> 9, c = idx & (CC - 1);
        float v = x[b * TT * CC + c];       // x[b, 0, c]
        g_y[idx] = v;
        g_a[idx] = __float2bfloat16(v);
        out[b * TT * CC + c] = v;           // out[b, 0, c]
    }
}

// ---------------- launcher: exactly 2 graph nodes ----------------
extern "C" void kernel_launch(void* const* d_in, const int* in_sizes, int n_in,
                              void* d_out, int out_size)
{
    const float* x  = (const float*)d_in[0];
    const float* W1 = (const float*)d_in[1];
    const float* b1 = (const float*)d_in[2];
    const float* W2 = (const float*)d_in[3];
    const float* b2 = (const float*)d_in[4];
    const float* W3 = (const float*)d_in[5];
    const float* b3 = (const float*)d_in[6];
    float* out = (float*)d_out;

    (void)in_sizes; (void)n_in; (void)out_size;

    prep_kernel<<<(HH * HH + 255) / 256, 256>>>(x, W1, W2, W3, out);
    ode_kernel<<<NCTA, 256>>>(b1, b2, b3, out);
}

// round 7
// speedup vs baseline: 1.2344x; 1.2344x over previous
#include <cuda_runtime.h>
#include <cuda_bf16.h>
#include <stdint.h>

// Problem constants
#define BB 128
#define TT 256
#define CC 512
#define HH 2048
#define NCTA 64

__device__ __constant__ float k_DT      = (float)(1.0/765.0);
__device__ __constant__ float k_HALF_DT = (float)(0.5/765.0);
__device__ __constant__ float k_SIXTH   = (float)(1.0/(765.0*6.0));

// ---------------- device-global scratch (no runtime allocation) ----------------
// Weights pre-packed into mma.m16n8k16 B-fragment register order:
//   u32 index within a CTA/group block: q = ((t*WN + wn)*NF + nf)*64 + lane*2 + reg
//   value = pack(W[k][n], W[k+1][n]) with k = t*16 + (lane&3)*2 + reg*8,
//                                        n = nbase + wn*NF*8 + nf*8 + (lane>>2)
__device__ __align__(16) uint32_t g_W1p[NCTA * 8192];    // 64 CTAs x (512*32/2)
__device__ __align__(16) uint32_t g_W2p[NCTA * 32768];   // 64 CTAs x (2048*32/2)
__device__ __align__(16) uint32_t g_W3p[32 * 16384];     // 32 grps x (2048*16/2)

__device__ __align__(16) __nv_bfloat16 g_a [BB*CC];      // bf16 MLP input
__device__ __align__(16) __nv_bfloat16 g_h1[BB*HH];
__device__ __align__(16) __nv_bfloat16 g_h2[BB*HH];
__device__ float g_y [BB*CC];                            // fp32 ODE state
__device__ float g_ks[BB*CC];                            // fp32 RK4 k-sum

// ---------------- grid barrier ----------------
__device__ unsigned g_count;
__device__ volatile unsigned g_gen;

__device__ __forceinline__ void grid_barrier(unsigned &gen){
    __syncthreads();
    if (threadIdx.x == 0){
        __threadfence();
        if (atomicAdd(&g_count, 1u) == gridDim.x - 1u){
            atomicExch(&g_count, 0u);
            __threadfence();
            g_gen = gen + 1u;
        } else {
            while (g_gen == gen) { }
            __threadfence();
        }
    }
    __syncthreads();
    gen++;
}

// ---------------- PTX helpers ----------------
__device__ __forceinline__ void cp16(void* s, const void* g){
    uint32_t sa = (uint32_t)__cvta_generic_to_shared(s);
    asm volatile("cp.async.cg.shared.global [%0], [%1], 16;\n" :: "r"(sa), "l"(g));
}
__device__ __forceinline__ void cpcommit(){ asm volatile("cp.async.commit_group;\n"); }
template<int N> __device__ __forceinline__ void cpwait(){
    asm volatile("cp.async.wait_group %0;\n" :: "n"(N));
}

__device__ __forceinline__ void mma16816(float* c, const uint32_t* a, const uint32_t* b){
    asm volatile(
        "mma.sync.aligned.m16n8k16.row.col.f32.bf16.bf16.f32 "
        "{%0,%1,%2,%3},{%4,%5,%6,%7},{%8,%9},{%0,%1,%2,%3};\n"
        : "+f"(c[0]), "+f"(c[1]), "+f"(c[2]), "+f"(c[3])
        : "r"(a[0]), "r"(a[1]), "r"(a[2]), "r"(a[3]), "r"(b[0]), "r"(b[1]));
}

__device__ __forceinline__ void ldsm4(uint32_t* a, const __nv_bfloat16* p){
    uint32_t addr = (uint32_t)__cvta_generic_to_shared(p);
    asm volatile("ldmatrix.sync.aligned.m8n8.x4.shared.b16 {%0,%1,%2,%3},[%4];\n"
        : "=r"(a[0]), "=r"(a[1]), "=r"(a[2]), "=r"(a[3]) : "r"(addr));
}

__device__ __forceinline__ uint32_t packbf(__nv_bfloat16 lo, __nv_bfloat16 hi){
    union { __nv_bfloat162 v; uint32_t u; } t;
    t.v.x = lo; t.v.y = hi; return t.u;
}
__device__ __forceinline__ float fast_tanh(float x){
    float y; asm("tanh.approx.f32 %0, %1;" : "=f"(y) : "f"(x)); return y;
}

// ---------------- smem layout (dynamic, 231424 B = 226 KB) ----------------
// [0      , 131072) W2s  resident packed W2 slice (u32[32768])
// [131072 , 196608) W3s  resident packed W3 slice (u32[16384])
// [196608 , 227328) As   3 stages x 5120 bf16 (L1/L2: [128][40], L3: [64][72])
// [227328 , 231424) Bs   2 stages x 512 u32 (W1 chunk stream)
#define SMEM_BYTES 231424

// ---------------- layers 1 & 2: D = tanh(A @ W + b) -> bf16 ----------------
// Tile 128 x 32, warps 4x2, MF=2, NF=2, KC=32.
template<int KDIM, bool STREAM_B>
__device__ __forceinline__ void layer12(
    const __nv_bfloat16* __restrict__ Ag,
    const uint32_t* __restrict__ Bres,   // resident W2s or global W1p base
    uint32_t* __restrict__ Bs,
    __nv_bfloat16* __restrict__ As,
    __nv_bfloat16* __restrict__ Og,
    const float br[2][2],
    int tid, int lane, int wm, int wn, int g8, int t4, int nb)
{
    constexpr int NC   = KDIM / 32;
    constexpr int STG  = STREAM_B ? 2 : 3;
    constexpr int DIST = STREAM_B ? 1 : 2;

    float acc[2][2][4];
    #pragma unroll
    for (int i=0;i<2;i++)
        #pragma unroll
        for (int j=0;j<2;j++)
            #pragma unroll
            for (int q=0;q<4;q++) acc[i][j][q] = 0.f;

    auto loadChunk = [&](int c, int st){
        __nv_bfloat16* dst = As + st * 5120;
        const __nv_bfloat16* src = Ag + c * 32;
        #pragma unroll
        for (int i=0;i<2;i++){
            int task = tid*2 + i;
            int row = task >> 2, seg = task & 3;
            cp16(dst + row*40 + seg*8, src + row*KDIM + seg*8);
        }
        if (STREAM_B && tid < 128)
            cp16(Bs + st*512 + tid*4, Bres + c*512 + tid*4);
    };

    #pragma unroll
    for (int d=0; d<DIST; d++){ loadChunk(d, d); cpcommit(); }

    for (int c=0; c<NC; c++){
        cpwait<DIST-1>();
        __syncthreads();
        const int st = c % STG;
        { int cn = c + DIST; if (cn < NC) loadChunk(cn, cn % STG); cpcommit(); }

        const __nv_bfloat16* Ast = As + st * 5120;
        const uint32_t* Bsrc = STREAM_B ? (Bs + st*512) : Bres;
        #pragma unroll
        for (int ks=0; ks<2; ks++){
            uint32_t a[2][4];
            #pragma unroll
            for (int mf=0; mf<2; mf++)
                ldsm4(a[mf], Ast + (wm*32 + mf*16 + (lane&15))*40 + ks*16 + (lane>>4)*8);
            uint2 bp[2];
            #pragma unroll
            for (int nf=0; nf<2; nf++){
                int tloc = STREAM_B ? ks : (c*2 + ks);
                bp[nf] = *reinterpret_cast<const uint2*>(
                    Bsrc + ((((tloc*2 + wn)*2 + nf)*32) + lane)*2);
            }
            #pragma unroll
            for (int mf=0; mf<2; mf++)
                #pragma unroll
                for (int nf=0; nf<2; nf++)
                    mma16816(acc[mf][nf], a[mf], reinterpret_cast<const uint32_t*>(&bp[nf]));
        }
    }

    #pragma unroll
    for (int mf=0; mf<2; mf++)
        #pragma unroll
        for (int nf=0; nf<2; nf++){
            int r0 = wm*32 + mf*16 + g8;
            int gc = nb + wn*16 + nf*8 + t4*2;
            float* v = acc[mf][nf];
            union { __nv_bfloat162 v2; uint32_t u; } x0, x1;
            x0.v2.x = __float2bfloat16(fast_tanh(v[0] + br[nf][0]));
            x0.v2.y = __float2bfloat16(fast_tanh(v[1] + br[nf][1]));
            x1.v2.x = __float2bfloat16(fast_tanh(v[2] + br[nf][0]));
            x1.v2.y = __float2bfloat16(fast_tanh(v[3] + br[nf][1]));
            *reinterpret_cast<uint32_t*>(&Og[r0 * HH + gc])       = x0.u;
            *reinterpret_cast<uint32_t*>(&Og[(r0 + 8) * HH + gc]) = x1.u;
        }
}

// ---------------- RK4 bookkeeping ----------------
__device__ __forceinline__ void rk_ep(int r, int c, float k, int stage, int out_t,
                                      float* __restrict__ out)
{
    int idx = r * CC + c;
    if (stage == 3){
        float total = g_ks[idx] + k;
        float yn = fmaf(k_SIXTH, total, g_y[idx]);
        g_y[idx] = yn;
        g_a[idx] = __float2bfloat16(yn);
        if (out_t >= 0) out[r * TT * CC + out_t * CC + c] = yn;
    } else {
        float ks = (stage == 0) ? k : fmaf(2.f, k, g_ks[idx]);
        g_ks[idx] = ks;
        float al = (stage == 2) ? k_DT : k_HALF_DT;
        g_a[idx] = __float2bfloat16(fmaf(al, k, g_y[idx]));
    }
}

// ---------------- layer 3: k = h2 @ W3 + b3, fused RK4 ----------------
// Tile 64 x 16 (M-half x 16 cols), warps 4x2, MF=1, NF=1, KC=64 -> 32 chunks.
__device__ __forceinline__ void layer3(
    const __nv_bfloat16* __restrict__ Ag,     // g_h2 + mb3*HH
    const uint32_t* __restrict__ W3s,
    __nv_bfloat16* __restrict__ As,
    const float b3r[2],
    int s, int out_t, float* __restrict__ out,
    int tid, int lane, int wm, int wn, int g8, int t4, int mb3, int nb3)
{
    float acc[4] = {0.f, 0.f, 0.f, 0.f};

    auto loadChunk = [&](int c, int st){
        __nv_bfloat16* dst = As + st * 5120;
        const __nv_bfloat16* src = Ag + c * 64;
        #pragma unroll
        for (int i=0;i<2;i++){
            int task = tid*2 + i;
            int row = task >> 3, seg = task & 7;
            cp16(dst + row*72 + seg*8, src + row*HH + seg*8);
        }
    };

    loadChunk(0, 0); cpcommit();
    loadChunk(1, 1); cpcommit();

    for (int c=0; c<32; c++){
        cpwait<1>();
        __syncthreads();
        const int st = c % 3;
        { int cn = c + 2; if (cn < 32) loadChunk(cn, cn % 3); cpcommit(); }

        const __nv_bfloat16* Ast = As + st * 5120;
        #pragma unroll
        for (int ks=0; ks<4; ks++){
            uint32_t a[4];
            ldsm4(a, Ast + (wm*16 + (lane&15))*72 + ks*16 + (lane>>4)*8);
            uint2 bp = *reinterpret_cast<const uint2*>(
                W3s + (((c*4 + ks)*2 + wn)*32 + lane)*2);
            mma16816(acc, a, reinterpret_cast<const uint32_t*>(&bp));
        }
    }

    int r0 = mb3 + wm*16 + g8;
    int gc = nb3 + wn*8 + t4*2;
    rk_ep(r0,     gc,     acc[0] + b3r[0], s, out_t, out);
    rk_ep(r0,     gc + 1, acc[1] + b3r[1], s, out_t, out);
    rk_ep(r0 + 8, gc,     acc[2] + b3r[0], s, out_t, out);
    rk_ep(r0 + 8, gc + 1, acc[3] + b3r[1], s, out_t, out);
}

// ---------------- persistent kernel ----------------
__global__ void __launch_bounds__(256, 1)
ode_kernel(const float* __restrict__ b1,
           const float* __restrict__ b2,
           const float* __restrict__ b3,
           float* __restrict__ out)
{
    extern __shared__ __align__(16) char smem[];
    uint32_t*      W2s = reinterpret_cast<uint32_t*>(smem);
    uint32_t*      W3s = reinterpret_cast<uint32_t*>(smem + 131072);
    __nv_bfloat16* As  = reinterpret_cast<__nv_bfloat16*>(smem + 196608);
    uint32_t*      Bs  = reinterpret_cast<uint32_t*>(smem + 227328);

    const int tid  = threadIdx.x;
    const int lane = tid & 31;
    const int warp = tid >> 5;
    const int wm   = warp & 3;
    const int wn   = warp >> 2;
    const int g8   = lane >> 2;
    const int t4   = lane & 3;
    const int cta  = blockIdx.x;
    const int nb   = cta * 32;            // L1/L2 column base
    const int mb3  = (cta >> 5) * 64;     // L3 row base
    const int grp3 = cta & 31;
    const int nb3  = grp3 * 16;           // L3 column base

    // one-time: resident weight slices -> smem
    {
        const uint32_t* s2 = g_W2p + cta * 32768;
        #pragma unroll
        for (int i=0;i<32;i++) cp16(W2s + (tid + i*256)*4, s2 + (tid + i*256)*4);
        const uint32_t* s3 = g_W3p + grp3 * 16384;
        #pragma unroll
        for (int i=0;i<16;i++) cp16(W3s + (tid + i*256)*4, s3 + (tid + i*256)*4);
        cpcommit(); cpwait<0>(); __syncthreads();
    }

    // bias registers
    float b1r[2][2], b2r[2][2], b3r[2];
    #pragma unroll
    for (int nf=0; nf<2; nf++){
        int c = nb + wn*16 + nf*8 + t4*2;
        b1r[nf][0] = b1[c]; b1r[nf][1] = b1[c+1];
        b2r[nf][0] = b2[c]; b2r[nf][1] = b2[c+1];
    }
    { int c = nb3 + wn*8 + t4*2; b3r[0] = b3[c]; b3r[1] = b3[c+1]; }

    const uint32_t* W1g = g_W1p + cta * 8192;
    unsigned gen = 0;

    for (int t = 1; t < TT; t++){
        for (int sub = 0; sub < 3; sub++){
            for (int s = 0; s < 4; s++){
                layer12<CC, true >(g_a,  W1g, Bs, As, g_h1, b1r,
                                   tid, lane, wm, wn, g8, t4, nb);
                grid_barrier(gen);
                layer12<HH, false>(g_h1, W2s, Bs, As, g_h2, b2r,
                                   tid, lane, wm, wn, g8, t4, nb);
                grid_barrier(gen);
                const int out_t = (s == 3 && sub == 2) ? t : -1;
                layer3(g_h2 + mb3 * HH, W3s, As, b3r, s, out_t, out,
                       tid, lane, wm, wn, g8, t4, mb3, nb3);
                grid_barrier(gen);
            }
        }
    }
}

// ---------------- prep: pack weights to fragment order, init state ----------------
__global__ void prep_kernel(const float* __restrict__ x,
                            const float* __restrict__ W1,
                            const float* __restrict__ W2,
                            const float* __restrict__ W3,
                            float* __restrict__ out)
{
    int i = blockIdx.x * blockDim.x + threadIdx.x;
    if (i == 0){ g_count = 0; g_gen = 0; }

    if (i < NCTA * 32768){                 // W2 pack
        int cta = i >> 15, q = i & 32767;
        int reg = q & 1, lane = (q >> 1) & 31, u = q >> 6;
        int nf = u & 1, wn = (u >> 1) & 1, tt = u >> 2;
        int n = cta*32 + wn*16 + nf*8 + (lane >> 2);
        int k = tt*16 + (lane & 3)*2 + reg*8;
        g_W2p[i] = packbf(__float2bfloat16(W2[k*HH + n]),
                          __float2bfloat16(W2[(k+1)*HH + n]));
    }
    if (i < NCTA * 8192){                  // W1 pack
        int cta = i >> 13, q = i & 8191;
        int reg = q & 1, lane = (q >> 1) & 31, u = q >> 6;
        int nf = u & 1, wn = (u >> 1) & 1, tt = u >> 2;
        int n = cta*32 + wn*16 + nf*8 + (lane >> 2);
        int k = tt*16 + (lane & 3)*2 + reg*8;
        g_W1p[i] = packbf(__float2bfloat16(W1[k*HH + n]),
                          __float2bfloat16(W1[(k+1)*HH + n]));
    }
    if (i < 32 * 16384){                   // W3 pack (NF=1)
        int grp = i >> 14, q = i & 16383;
        int reg = q & 1, lane = (q >> 1) & 31, u = q >> 6;
        int wn = u & 1, tt = u >> 1;
        int n = grp*16 + wn*8 + (lane >> 2);
        int k = tt*16 + (lane & 3)*2 + reg*8;
        g_W3p[i] = packbf(__float2bfloat16(W3[k*CC + n]),
                          __float2bfloat16(W3[(k+1)*CC + n]));
    }
    if (i < BB * CC){                      // state init
        int b = i >> 9, c = i & (CC - 1);
        float v = x[b * TT * CC + c];
        g_y[i] = v;
        g_a[i] = __float2bfloat16(v);
        out[b * TT * CC + c] = v;
    }
}

// ---------------- launcher: 2 graph nodes ----------------
extern "C" void kernel_launch(void* const* d_in, const int* in_sizes, int n_in,
                              void* d_out, int out_size)
{
    const float* x  = (const float*)d_in[0];
    const float* W1 = (const float*)d_in[1];
    const float* b1 = (const float*)d_in[2];
    const float* W2 = (const float*)d_in[3];
    const float* b2 = (const float*)d_in[4];
    const float* W3 = (const float*)d_in[5];
    const float* b3 = (const float*)d_in[6];
    float* out = (float*)d_out;

    (void)in_sizes; (void)n_in; (void)out_size;

    cudaFuncSetAttribute(ode_kernel, cudaFuncAttributeMaxDynamicSharedMemorySize,
                         SMEM_BYTES);

    prep_kernel<<<(NCTA * 32768 + 255) / 256, 256>>>(x, W1, W2, W3, out);
    ode_kernel<<<NCTA, 256, SMEM_BYTES>>>(b1, b2, b3, out);
}

// round 8
// speedup vs baseline: 1.5781x; 1.2785x over previous
#include <cuda_runtime.h>
#include <cuda_bf16.h>
#include <stdint.h>

// Problem constants
#define BB 128
#define TT 256
#define CC 512
#define HH 2048
#define NCTA 64

__device__ __constant__ float k_DT      = (float)(1.0/765.0);
__device__ __constant__ float k_HALF_DT = (float)(0.5/765.0);
__device__ __constant__ float k_SIXTH   = (float)(1.0/(765.0*6.0));

// ---------------- device-global scratch (no runtime allocation) ----------------
// Weights pre-packed in mma.m16n8k16 B-fragment register order (see prep_kernel).
__device__ __align__(16) uint32_t g_W1p[NCTA * 8192];    // 64 CTAs x (512*32/2)
__device__ __align__(16) uint32_t g_W2p[NCTA * 32768];   // 64 CTAs x (2048*32/2)
__device__ __align__(16) uint32_t g_W3p[32 * 16384];     // 32 grps x (2048*16/2)

__device__ __align__(16) __nv_bfloat16 g_a [BB*CC];      // bf16 MLP input
__device__ __align__(16) __nv_bfloat16 g_h1[BB*HH];
__device__ __align__(16) __nv_bfloat16 g_h2[BB*HH];
__device__ float g_y [BB*CC];                            // fp32 ODE state
__device__ float g_ks[BB*CC];                            // fp32 RK4 k-sum

// ---------------- grid barrier ----------------
__device__ unsigned g_count;
__device__ volatile unsigned g_gen;

__device__ __forceinline__ void grid_barrier(unsigned &gen){
    __syncthreads();
    if (threadIdx.x == 0){
        __threadfence();
        if (atomicAdd(&g_count, 1u) == gridDim.x - 1u){
            atomicExch(&g_count, 0u);
            __threadfence();
            g_gen = gen + 1u;
        } else {
            while (g_gen == gen) { }
            __threadfence();
        }
    }
    __syncthreads();
    gen++;
}

// ---------------- PTX helpers ----------------
__device__ __forceinline__ void cp16(void* s, const void* g){
    uint32_t sa = (uint32_t)__cvta_generic_to_shared(s);
    asm volatile("cp.async.cg.shared.global [%0], [%1], 16;\n" :: "r"(sa), "l"(g));
}
__device__ __forceinline__ void cpcommit(){ asm volatile("cp.async.commit_group;\n"); }
template<int N> __device__ __forceinline__ void cpwait(){
    asm volatile("cp.async.wait_group %0;\n" :: "n"(N));
}
// wait so that "allow" groups may remain pending (exact tail handling)
__device__ __forceinline__ void cpwait_dyn(int allow){
    if (allow >= 2)      cpwait<2>();
    else if (allow == 1) cpwait<1>();
    else                 cpwait<0>();
}

__device__ __forceinline__ void mma16816(float* c, const uint32_t* a, const uint32_t* b){
    asm volatile(
        "mma.sync.aligned.m16n8k16.row.col.f32.bf16.bf16.f32 "
        "{%0,%1,%2,%3},{%4,%5,%6,%7},{%8,%9},{%0,%1,%2,%3};\n"
        : "+f"(c[0]), "+f"(c[1]), "+f"(c[2]), "+f"(c[3])
        : "r"(a[0]), "r"(a[1]), "r"(a[2]), "r"(a[3]), "r"(b[0]), "r"(b[1]));
}

__device__ __forceinline__ void ldsm4(uint32_t* a, const __nv_bfloat16* p){
    uint32_t addr = (uint32_t)__cvta_generic_to_shared(p);
    asm volatile("ldmatrix.sync.aligned.m8n8.x4.shared.b16 {%0,%1,%2,%3},[%4];\n"
        : "=r"(a[0]), "=r"(a[1]), "=r"(a[2]), "=r"(a[3]) : "r"(addr));
}

__device__ __forceinline__ uint32_t packbf(__nv_bfloat16 lo, __nv_bfloat16 hi){
    union { __nv_bfloat162 v; uint32_t u; } t;
    t.v.x = lo; t.v.y = hi; return t.u;
}
__device__ __forceinline__ float fast_tanh(float x){
    float y; asm("tanh.approx.f32 %0, %1;" : "=f"(y) : "f"(x)); return y;
}

// ---------------- smem layout (dynamic) ----------------
// A stages: 4 x [128 rows x 136 bf16] = 4 x 34816 B = 139264 B
// B stages: 4 x 2048 u32             = 4 x  8192 B =  32768 B
#define ASZ 17408          /* bf16 elems per A stage */
#define SA  136            /* padded A row (bf16)    */
#define BSZ 2048           /* u32 per B stage        */
#define SMEM_BYTES (4*34816 + 4*8192)
#define DIST 3

// ---------------- layers 1 & 2: D = tanh(A @ W + b) -> bf16 ----------------
// Tile 128x32, warps 4x2, MF=2, NF=2, KC=128.
template<int KDIM>
__device__ __forceinline__ void layer12(
    const __nv_bfloat16* __restrict__ Ag,
    const uint32_t* __restrict__ Bg,      // packed weight slice for this CTA
    __nv_bfloat16* __restrict__ As,
    uint32_t* __restrict__ Bs,
    __nv_bfloat16* __restrict__ Og,
    const float br[2][2],
    int tid, int lane, int wm, int wn, int g8, int t4, int nb)
{
    constexpr int NC = KDIM / 128;

    float acc[2][2][4];
    #pragma unroll
    for (int i=0;i<2;i++)
        #pragma unroll
        for (int j=0;j<2;j++)
            #pragma unroll
            for (int q=0;q<4;q++) acc[i][j][q] = 0.f;

    auto loadChunk = [&](int c, int st){
        __nv_bfloat16* dst = As + st * ASZ;
        const __nv_bfloat16* src = Ag + c * 128;
        #pragma unroll
        for (int i=0;i<8;i++){                  // 2048 x 16B A tasks
            int task = i*256 + tid;
            int row = task >> 4, seg = task & 15;
            cp16(dst + row*SA + seg*8, src + row*KDIM + seg*8);
        }
        const uint32_t* bsrc = Bg + c * 2048;
        #pragma unroll
        for (int i=0;i<2;i++){                  // 512 x 16B B tasks
            int task = i*256 + tid;
            cp16(Bs + st*BSZ + task*4, bsrc + task*4);
        }
    };

    #pragma unroll
    for (int d=0; d<DIST && d<NC; d++){ loadChunk(d, d); cpcommit(); }

    for (int c=0; c<NC; c++){
        cpwait_dyn(min(DIST-1, NC-1-c));
        __syncthreads();
        { int cn = c + DIST; if (cn < NC) loadChunk(cn, cn & 3); cpcommit(); }

        const __nv_bfloat16* Ast = As + (c & 3) * ASZ;
        const uint32_t*      Bst = Bs + (c & 3) * BSZ;
        #pragma unroll
        for (int ks=0; ks<8; ks++){
            uint32_t a[2][4];
            #pragma unroll
            for (int mf=0; mf<2; mf++)
                ldsm4(a[mf], Ast + (wm*32 + mf*16 + (lane&15))*SA
                              + ks*16 + (lane>>4)*8);
            uint2 bp[2];
            #pragma unroll
            for (int nf=0; nf<2; nf++)
                bp[nf] = *reinterpret_cast<const uint2*>(
                    Bst + (((ks*2 + wn)*2 + nf)*32 + lane)*2);
            #pragma unroll
            for (int mf=0; mf<2; mf++)
                #pragma unroll
                for (int nf=0; nf<2; nf++)
                    mma16816(acc[mf][nf], a[mf],
                             reinterpret_cast<const uint32_t*>(&bp[nf]));
        }
    }

    #pragma unroll
    for (int mf=0; mf<2; mf++)
        #pragma unroll
        for (int nf=0; nf<2; nf++){
            int r0 = wm*32 + mf*16 + g8;
            int gc = nb + wn*16 + nf*8 + t4*2;
            float* v = acc[mf][nf];
            union { __nv_bfloat162 v2; uint32_t u; } x0, x1;
            x0.v2.x = __float2bfloat16(fast_tanh(v[0] + br[nf][0]));
            x0.v2.y = __float2bfloat16(fast_tanh(v[1] + br[nf][1]));
            x1.v2.x = __float2bfloat16(fast_tanh(v[2] + br[nf][0]));
            x1.v2.y = __float2bfloat16(fast_tanh(v[3] + br[nf][1]));
            *reinterpret_cast<uint32_t*>(&Og[r0 * HH + gc])       = x0.u;
            *reinterpret_cast<uint32_t*>(&Og[(r0 + 8) * HH + gc]) = x1.u;
        }
}

// ---------------- RK4 bookkeeping ----------------
__device__ __forceinline__ void rk_ep(int r, int c, float k, int stage, int out_t,
                                      float* __restrict__ out)
{
    int idx = r * CC + c;
    if (stage == 3){
        float total = g_ks[idx] + k;
        float yn = fmaf(k_SIXTH, total, g_y[idx]);
        g_y[idx] = yn;
        g_a[idx] = __float2bfloat16(yn);
        if (out_t >= 0) out[r * TT * CC + out_t * CC + c] = yn;
    } else {
        float ks = (stage == 0) ? k : fmaf(2.f, k, g_ks[idx]);
        g_ks[idx] = ks;
        float al = (stage == 2) ? k_DT : k_HALF_DT;
        g_a[idx] = __float2bfloat16(fmaf(al, k, g_y[idx]));
    }
}

// ---------------- layer 3: k = h2 @ W3 + b3, fused RK4 ----------------
// Tile 64x16, warps 4x2, MF=1, NF=1, KC=128 -> 16 chunks.
__device__ __forceinline__ void layer3(
    const __nv_bfloat16* __restrict__ Ag,     // g_h2 + mb3*HH
    const uint32_t* __restrict__ Bg,          // packed W3 slice
    __nv_bfloat16* __restrict__ As,
    uint32_t* __restrict__ Bs,
    const float b3r[2],
    int s, int out_t, float* __restrict__ out,
    int tid, int lane, int wm, int wn, int g8, int t4, int mb3, int nb3)
{
    constexpr int NC = 16;
    float acc[4] = {0.f, 0.f, 0.f, 0.f};

    auto loadChunk = [&](int c, int st){
        __nv_bfloat16* dst = As + st * ASZ;
        const __nv_bfloat16* src = Ag + c * 128;
        #pragma unroll
        for (int i=0;i<4;i++){                  // 1024 x 16B A tasks (64 rows)
            int task = i*256 + tid;
            int row = task >> 4, seg = task & 15;
            cp16(dst + row*SA + seg*8, src + row*HH + seg*8);
        }
        cp16(Bs + st*BSZ + tid*4, Bg + c*1024 + tid*4);   // 256 x 16B B tasks
    };

    #pragma unroll
    for (int d=0; d<DIST; d++){ loadChunk(d, d); cpcommit(); }

    for (int c=0; c<NC; c++){
        cpwait_dyn(min(DIST-1, NC-1-c));
        __syncthreads();
        { int cn = c + DIST; if (cn < NC) loadChunk(cn, cn & 3); cpcommit(); }

        const __nv_bfloat16* Ast = As + (c & 3) * ASZ;
        const uint32_t*      Bst = Bs + (c & 3) * BSZ;
        #pragma unroll
        for (int ks=0; ks<8; ks++){
            uint32_t a[4];
            ldsm4(a, Ast + (wm*16 + (lane&15))*SA + ks*16 + (lane>>4)*8);
            uint2 bp = *reinterpret_cast<const uint2*>(
                Bst + ((ks*2 + wn)*32 + lane)*2);
            mma16816(acc, a, reinterpret_cast<const uint32_t*>(&bp));
        }
    }

    int r0 = mb3 + wm*16 + g8;
    int gc = nb3 + wn*8 + t4*2;
    rk_ep(r0,     gc,     acc[0] + b3r[0], s, out_t, out);
    rk_ep(r0,     gc + 1, acc[1] + b3r[1], s, out_t, out);
    rk_ep(r0 + 8, gc,     acc[2] + b3r[0], s, out_t, out);
    rk_ep(r0 + 8, gc + 1, acc[3] + b3r[1], s, out_t, out);
}

// ---------------- persistent kernel ----------------
__global__ void __launch_bounds__(256, 1)
ode_kernel(const float* __restrict__ b1,
           const float* __restrict__ b2,
           const float* __restrict__ b3,
           float* __restrict__ out)
{
    extern __shared__ __align__(16) char smem[];
    __nv_bfloat16* As = reinterpret_cast<__nv_bfloat16*>(smem);
    uint32_t*      Bs = reinterpret_cast<uint32_t*>(smem + 4*34816);

    const int tid  = threadIdx.x;
    const int lane = tid & 31;
    const int warp = tid >> 5;
    const int wm   = warp & 3;
    const int wn   = warp >> 2;
    const int g8   = lane >> 2;
    const int t4   = lane & 3;
    const int cta  = blockIdx.x;
    const int nb   = cta * 32;            // L1/L2 column base
    const int mb3  = (cta >> 5) * 64;     // L3 row base
    const int grp3 = cta & 31;
    const int nb3  = grp3 * 16;           // L3 column base

    // bias registers
    float b1r[2][2], b2r[2][2], b3r[2];
    #pragma unroll
    for (int nf=0; nf<2; nf++){
        int c = nb + wn*16 + nf*8 + t4*2;
        b1r[nf][0] = b1[c]; b1r[nf][1] = b1[c+1];
        b2r[nf][0] = b2[c]; b2r[nf][1] = b2[c+1];
    }
    { int c = nb3 + wn*8 + t4*2; b3r[0] = b3[c]; b3r[1] = b3[c+1]; }

    const uint32_t* W1g = g_W1p + cta * 8192;
    const uint32_t* W2g = g_W2p + cta * 32768;
    const uint32_t* W3g = g_W3p + grp3 * 16384;
    unsigned gen = 0;

    for (int t = 1; t < TT; t++){
        for (int sub = 0; sub < 3; sub++){
            for (int s = 0; s < 4; s++){
                layer12<CC>(g_a,  W1g, As, Bs, g_h1, b1r,
                            tid, lane, wm, wn, g8, t4, nb);
                grid_barrier(gen);
                layer12<HH>(g_h1, W2g, As, Bs, g_h2, b2r,
                            tid, lane, wm, wn, g8, t4, nb);
                grid_barrier(gen);
                const int out_t = (s == 3 && sub == 2) ? t : -1;
                layer3(g_h2 + mb3 * HH, W3g, As, Bs, b3r, s, out_t, out,
                       tid, lane, wm, wn, g8, t4, mb3, nb3);
                grid_barrier(gen);
            }
        }
    }
}

// ---------------- prep: pack weights to fragment order, init state ----------------
__global__ void prep_kernel(const float* __restrict__ x,
                            const float* __restrict__ W1,
                            const float* __restrict__ W2,
                            const float* __restrict__ W3,
                            float* __restrict__ out)
{
    int i = blockIdx.x * blockDim.x + threadIdx.x;
    if (i == 0){ g_count = 0; g_gen = 0; }

    if (i < NCTA * 32768){                 // W2 pack
        int cta = i >> 15, q = i & 32767;
        int reg = q & 1, lane = (q >> 1) & 31, u = q >> 6;
        int nf = u & 1, wn = (u >> 1) & 1, tt = u >> 2;
        int n = cta*32 + wn*16 + nf*8 + (lane >> 2);
        int k = tt*16 + (lane & 3)*2 + reg*8;
        g_W2p[i] = packbf(__float2bfloat16(W2[k*HH + n]),
                          __float2bfloat16(W2[(k+1)*HH + n]));
    }
    if (i < NCTA * 8192){                  // W1 pack
        int cta = i >> 13, q = i & 8191;
        int reg = q & 1, lane = (q >> 1) & 31, u = q >> 6;
        int nf = u & 1, wn = (u >> 1) & 1, tt = u >> 2;
        int n = cta*32 + wn*16 + nf*8 + (lane >> 2);
        int k = tt*16 + (lane & 3)*2 + reg*8;
        g_W1p[i] = packbf(__float2bfloat16(W1[k*HH + n]),
                          __float2bfloat16(W1[(k+1)*HH + n]));
    }
    if (i < 32 * 16384){                   // W3 pack (NF=1)
        int grp = i >> 14, q = i & 16383;
        int reg = q & 1, lane = (q >> 1) & 31, u = q >> 6;
        int wn = u & 1, tt = u >> 1;
        int n = grp*16 + wn*8 + (lane >> 2);
        int k = tt*16 + (lane & 3)*2 + reg*8;
        g_W3p[i] = packbf(__float2bfloat16(W3[k*CC + n]),
                          __float2bfloat16(W3[(k+1)*CC + n]));
    }
    if (i < BB * CC){                      // state init
        int b = i >> 9, c = i & (CC - 1);
        float v = x[b * TT * CC + c];
        g_y[i] = v;
        g_a[i] = __float2bfloat16(v);
        out[b * TT * CC + c] = v;
    }
}

// ---------------- launcher: 2 graph nodes ----------------
extern "C" void kernel_launch(void* const* d_in, const int* in_sizes, int n_in,
                              void* d_out, int out_size)
{
    const float* x  = (const float*)d_in[0];
    const float* W1 = (const float*)d_in[1];
    const float* b1 = (const float*)d_in[2];
    const float* W2 = (const float*)d_in[3];
    const float* b2 = (const float*)d_in[4];
    const float* W3 = (const float*)d_in[5];
    const float* b3 = (const float*)d_in[6];
    float* out = (float*)d_out;

    (void)in_sizes; (void)n_in; (void)out_size;

    cudaFuncSetAttribute(ode_kernel, cudaFuncAttributeMaxDynamicSharedMemorySize,
                         SMEM_BYTES);

    prep_kernel<<<(NCTA * 32768 + 255) / 256, 256>>>(x, W1, W2, W3, out);
    ode_kernel<<<NCTA, 256, SMEM_BYTES>>>(b1, b2, b3, out);
}

// round 9
// speedup vs baseline: 2.1546x; 1.3653x over previous
#include <cuda_runtime.h>
#include <cuda_bf16.h>
#include <stdint.h>

// Problem constants
#define BB 128
#define TT 256
#define CC 512
#define HH 2048
#define NCTA 128          /* persistent grid */
#define NBLK 64           /* weight N-block count (32-col blocks of H) */

__device__ __constant__ float k_DT      = (float)(1.0/765.0);
__device__ __constant__ float k_HALF_DT = (float)(0.5/765.0);
__device__ __constant__ float k_SIXTH   = (float)(1.0/(765.0*6.0));

// ---------------- device-global scratch (no runtime allocation) ----------------
// Weights pre-packed in mma.m16n8k16 B-fragment register order (see prep_kernel).
__device__ __align__(16) uint32_t g_W1p[NBLK * 8192];    // 64 blks x (512*32/2)
__device__ __align__(16) uint32_t g_W2p[NBLK * 32768];   // 64 blks x (2048*32/2)
__device__ __align__(16) uint32_t g_W3p[32 * 16384];     // 32 grps x (2048*16/2)

__device__ __align__(16) __nv_bfloat16 g_a [BB*CC];      // bf16 MLP input
__device__ __align__(16) __nv_bfloat16 g_h1[BB*HH];
__device__ __align__(16) __nv_bfloat16 g_h2[BB*HH];
__device__ float g_y [BB*CC];                            // fp32 ODE state
__device__ float g_ks[BB*CC];                            // fp32 RK4 k-sum

// ---------------- grid barrier ----------------
__device__ unsigned g_count;
__device__ volatile unsigned g_gen;

__device__ __forceinline__ void grid_barrier(unsigned &gen){
    __syncthreads();
    if (threadIdx.x == 0){
        __threadfence();
        if (atomicAdd(&g_count, 1u) == gridDim.x - 1u){
            atomicExch(&g_count, 0u);
            __threadfence();
            g_gen = gen + 1u;
        } else {
            while (g_gen == gen) { }
            __threadfence();
        }
    }
    __syncthreads();
    gen++;
}

// ---------------- PTX helpers ----------------
__device__ __forceinline__ void cp16(void* s, const void* g){
    uint32_t sa = (uint32_t)__cvta_generic_to_shared(s);
    asm volatile("cp.async.cg.shared.global [%0], [%1], 16;\n" :: "r"(sa), "l"(g));
}
__device__ __forceinline__ void cpcommit(){ asm volatile("cp.async.commit_group;\n"); }
template<int N> __device__ __forceinline__ void cpwait(){
    asm volatile("cp.async.wait_group %0;\n" :: "n"(N));
}
__device__ __forceinline__ void cpwait_dyn(int allow){
    if (allow >= 2)      cpwait<2>();
    else if (allow == 1) cpwait<1>();
    else                 cpwait<0>();
}

__device__ __forceinline__ void mma16816(float* c, const uint32_t* a, const uint32_t* b){
    asm volatile(
        "mma.sync.aligned.m16n8k16.row.col.f32.bf16.bf16.f32 "
        "{%0,%1,%2,%3},{%4,%5,%6,%7},{%8,%9},{%0,%1,%2,%3};\n"
        : "+f"(c[0]), "+f"(c[1]), "+f"(c[2]), "+f"(c[3])
        : "r"(a[0]), "r"(a[1]), "r"(a[2]), "r"(a[3]), "r"(b[0]), "r"(b[1]));
}

__device__ __forceinline__ void ldsm4(uint32_t* a, const __nv_bfloat16* p){
    uint32_t addr = (uint32_t)__cvta_generic_to_shared(p);
    asm volatile("ldmatrix.sync.aligned.m8n8.x4.shared.b16 {%0,%1,%2,%3},[%4];\n"
        : "=r"(a[0]), "=r"(a[1]), "=r"(a[2]), "=r"(a[3]) : "r"(addr));
}

__device__ __forceinline__ uint32_t packbf(__nv_bfloat16 lo, __nv_bfloat16 hi){
    union { __nv_bfloat162 v; uint32_t u; } t;
    t.v.x = lo; t.v.y = hi; return t.u;
}
__device__ __forceinline__ float fast_tanh(float x){
    float y; asm("tanh.approx.f32 %0, %1;" : "=f"(y) : "f"(x)); return y;
}

// ---------------- smem layout (dynamic) ----------------
// A stages: 4 x 8704 bf16 (L1/L2: [64][136]; L3: [2 khalf][32][136]) = 69632 B
// B stages: 4 x 2048 u32                                             = 32768 B
// Red:      512 floats (L3 split-K reduction)                        =  2048 B
#define ASZ 8704
#define SA  136
#define BSZ 2048
#define SMEM_BYTES (4*17408 + 4*8192 + 2048)
#define DIST 3

// ---------------- layers 1 & 2: D = tanh(A @ W + b) -> bf16 ----------------
// Tile 64x32, warps 2(M)x4(N), MF=2, NF=1, KC=128.
template<int KDIM>
__device__ __forceinline__ void layer12(
    const __nv_bfloat16* __restrict__ Ag,   // pre-offset to tile row base
    const uint32_t* __restrict__ Bg,        // packed weight slice (N-block)
    __nv_bfloat16* __restrict__ As,
    uint32_t* __restrict__ Bs,
    __nv_bfloat16* __restrict__ Og,         // global out base (row 0)
    const float br[2],
    int tid, int lane, int wm, int wn, int g8, int t4, int mb, int nb)
{
    constexpr int NC = KDIM / 128;

    float acc[2][4];
    #pragma unroll
    for (int i=0;i<2;i++)
        #pragma unroll
        for (int q=0;q<4;q++) acc[i][q] = 0.f;

    auto loadChunk = [&](int c, int st){
        __nv_bfloat16* dst = As + st * ASZ;
        const __nv_bfloat16* src = Ag + c * 128;
        #pragma unroll
        for (int i=0;i<4;i++){                  // 1024 x 16B A tasks (64 rows)
            int task = i*256 + tid;
            int row = task >> 4, seg = task & 15;
            cp16(dst + row*SA + seg*8, src + row*KDIM + seg*8);
        }
        const uint32_t* bsrc = Bg + c * 2048;
        #pragma unroll
        for (int i=0;i<2;i++){                  // 512 x 16B B tasks
            int task = i*256 + tid;
            cp16(Bs + st*BSZ + task*4, bsrc + task*4);
        }
    };

    #pragma unroll
    for (int d=0; d<DIST && d<NC; d++){ loadChunk(d, d); cpcommit(); }

    for (int c=0; c<NC; c++){
        cpwait_dyn(min(DIST-1, NC-1-c));
        __syncthreads();
        { int cn = c + DIST; if (cn < NC) loadChunk(cn, cn & 3); cpcommit(); }

        const __nv_bfloat16* Ast = As + (c & 3) * ASZ;
        const uint32_t*      Bst = Bs + (c & 3) * BSZ;
        #pragma unroll
        for (int ks=0; ks<8; ks++){
            uint32_t a[2][4];
            #pragma unroll
            for (int mf=0; mf<2; mf++)
                ldsm4(a[mf], Ast + (wm*32 + mf*16 + (lane&15))*SA
                              + ks*16 + (lane>>4)*8);
            uint2 bp = *reinterpret_cast<const uint2*>(
                Bst + ((ks*4 + wn)*32 + lane)*2);
            #pragma unroll
            for (int mf=0; mf<2; mf++)
                mma16816(acc[mf], a[mf], reinterpret_cast<const uint32_t*>(&bp));
        }
    }

    #pragma unroll
    for (int mf=0; mf<2; mf++){
        int r0 = mb + wm*32 + mf*16 + g8;
        int gc = nb + wn*8 + t4*2;
        float* v = acc[mf];
        union { __nv_bfloat162 v2; uint32_t u; } x0, x1;
        x0.v2.x = __float2bfloat16(fast_tanh(v[0] + br[0]));
        x0.v2.y = __float2bfloat16(fast_tanh(v[1] + br[1]));
        x1.v2.x = __float2bfloat16(fast_tanh(v[2] + br[0]));
        x1.v2.y = __float2bfloat16(fast_tanh(v[3] + br[1]));
        *reinterpret_cast<uint32_t*>(&Og[r0 * HH + gc])       = x0.u;
        *reinterpret_cast<uint32_t*>(&Og[(r0 + 8) * HH + gc]) = x1.u;
    }
}

// ---------------- RK4 bookkeeping ----------------
__device__ __forceinline__ void rk_ep(int r, int c, float k, int stage, int out_t,
                                      float* __restrict__ out)
{
    int idx = r * CC + c;
    if (stage == 3){
        float total = g_ks[idx] + k;
        float yn = fmaf(k_SIXTH, total, g_y[idx]);
        g_y[idx] = yn;
        g_a[idx] = __float2bfloat16(yn);
        if (out_t >= 0) out[r * TT * CC + out_t * CC + c] = yn;
    } else {
        float ks = (stage == 0) ? k : fmaf(2.f, k, g_ks[idx]);
        g_ks[idx] = ks;
        float al = (stage == 2) ? k_DT : k_HALF_DT;
        g_a[idx] = __float2bfloat16(fmaf(al, k, g_y[idx]));
    }
}

// ---------------- layer 3: k = h2 @ W3 + b3, fused RK4 ----------------
// Tile 32x16, warps 2(M)x2(N)x2(K-half), KC=128 per half -> 8 chunk steps.
__device__ __forceinline__ void layer3(
    const __nv_bfloat16* __restrict__ Ag,     // g_h2 + mb3*HH
    const uint32_t* __restrict__ Bg,          // packed W3 slice (16-col grp)
    __nv_bfloat16* __restrict__ As,
    uint32_t* __restrict__ Bs,
    float* __restrict__ Red,
    const float b3r[2],
    int s, int out_t, float* __restrict__ out,
    int tid, int lane, int warp, int g8, int t4, int mb3, int nb3)
{
    constexpr int NC = 8;
    const int wm3 = warp & 1;
    const int wn3 = (warp >> 1) & 1;
    const int wk  = warp >> 2;

    float acc[4] = {0.f, 0.f, 0.f, 0.f};

    auto loadChunk = [&](int c, int st){
        __nv_bfloat16* dst = As + st * ASZ;
        #pragma unroll
        for (int i=0;i<4;i++){                  // 1024 A tasks: 2 kh x 32 rows x 16 segs
            int task = i*256 + tid;
            int kh = task >> 9, rem = task & 511;
            int row = rem >> 4, seg = rem & 15;
            cp16(dst + kh*(32*SA) + row*SA + seg*8,
                 Ag + row*HH + kh*1024 + c*128 + seg*8);
        }
        #pragma unroll
        for (int i=0;i<2;i++){                  // 512 B tasks: 2 kh x 1024 u32
            int task = i*256 + tid;
            int kh = task >> 8, j = task & 255;
            cp16(Bs + st*BSZ + kh*1024 + j*4,
                 Bg + kh*8192 + c*1024 + j*4);
        }
    };

    #pragma unroll
    for (int d=0; d<DIST; d++){ loadChunk(d, d); cpcommit(); }

    for (int c=0; c<NC; c++){
        cpwait_dyn(min(DIST-1, NC-1-c));
        __syncthreads();
        { int cn = c + DIST; if (cn < NC) loadChunk(cn, cn & 3); cpcommit(); }

        const __nv_bfloat16* Ast = As + (c & 3) * ASZ + wk*(32*SA);
        const uint32_t*      Bst = Bs + (c & 3) * BSZ + wk*1024;
        #pragma unroll
        for (int ks=0; ks<8; ks++){
            uint32_t a[4];
            ldsm4(a, Ast + (wm3*16 + (lane&15))*SA + ks*16 + (lane>>4)*8);
            uint2 bp = *reinterpret_cast<const uint2*>(
                Bst + ((ks*2 + wn3)*32 + lane)*2);
            mma16816(acc, a, reinterpret_cast<const uint32_t*>(&bp));
        }
    }

    // split-K reduction: wk=1 warps publish, wk=0 warps add + epilogue
    float* slot = Red + (wn3*2 + wm3)*128 + lane*4;
    if (wk == 1){
        slot[0] = acc[0]; slot[1] = acc[1]; slot[2] = acc[2]; slot[3] = acc[3];
    }
    __syncthreads();
    if (wk == 0){
        acc[0] += slot[0]; acc[1] += slot[1]; acc[2] += slot[2]; acc[3] += slot[3];
        int r0 = mb3 + wm3*16 + g8;
        int gc = nb3 + wn3*8 + t4*2;
        rk_ep(r0,     gc,     acc[0] + b3r[0], s, out_t, out);
        rk_ep(r0,     gc + 1, acc[1] + b3r[1], s, out_t, out);
        rk_ep(r0 + 8, gc,     acc[2] + b3r[0], s, out_t, out);
        rk_ep(r0 + 8, gc + 1, acc[3] + b3r[1], s, out_t, out);
    }
}

// ---------------- persistent kernel ----------------
__global__ void __launch_bounds__(256, 1)
ode_kernel(const float* __restrict__ b1,
           const float* __restrict__ b2,
           const float* __restrict__ b3,
           float* __restrict__ out)
{
    extern __shared__ __align__(16) char smem[];
    __nv_bfloat16* As  = reinterpret_cast<__nv_bfloat16*>(smem);
    uint32_t*      Bs  = reinterpret_cast<uint32_t*>(smem + 4*17408);
    float*         Red = reinterpret_cast<float*>(smem + 4*17408 + 4*8192);

    const int tid  = threadIdx.x;
    const int lane = tid & 31;
    const int warp = tid >> 5;
    const int wm   = warp & 1;            // L1/L2: M warp (2)
    const int wn   = warp >> 1;           // L1/L2: N warp (4)
    const int g8   = lane >> 2;
    const int t4   = lane & 3;
    const int cta  = blockIdx.x;
    const int mb   = (cta >> 6) * 64;     // L1/L2 row base (0 or 64)
    const int nb   = (cta & 63) * 32;     // L1/L2 column base
    const int mb3  = (cta >> 5) * 32;     // L3 row base
    const int nb3  = (cta & 31) * 16;     // L3 column base

    // bias registers
    float b1r[2], b2r[2], b3r[2];
    { int c = nb + wn*8 + t4*2;  b1r[0] = b1[c]; b1r[1] = b1[c+1];
                                 b2r[0] = b2[c]; b2r[1] = b2[c+1]; }
    { int c = nb3 + (((warp>>1)&1))*8 + t4*2; b3r[0] = b3[c]; b3r[1] = b3[c+1]; }

    const uint32_t* W1g = g_W1p + (cta & 63) * 8192;
    const uint32_t* W2g = g_W2p + (cta & 63) * 32768;
    const uint32_t* W3g = g_W3p + (cta & 31) * 16384;
    unsigned gen = 0;

    for (int t = 1; t < TT; t++){
        for (int sub = 0; sub < 3; sub++){
            for (int s = 0; s < 4; s++){
                layer12<CC>(g_a  + mb*CC, W1g, As, Bs, g_h1, b1r,
                            tid, lane, wm, wn, g8, t4, mb, nb);
                grid_barrier(gen);
                layer12<HH>(g_h1 + mb*HH, W2g, As, Bs, g_h2, b2r,
                            tid, lane, wm, wn, g8, t4, mb, nb);
                grid_barrier(gen);
                const int out_t = (s == 3 && sub == 2) ? t : -1;
                layer3(g_h2 + mb3*HH, W3g, As, Bs, Red, b3r, s, out_t, out,
                       tid, lane, warp, g8, t4, mb3, nb3);
                grid_barrier(gen);
            }
        }
    }
}

// ---------------- prep: pack weights to fragment order, init state ----------------
__global__ void prep_kernel(const float* __restrict__ x,
                            const float* __restrict__ W1,
                            const float* __restrict__ W2,
                            const float* __restrict__ W3,
                            float* __restrict__ out)
{
    int i = blockIdx.x * blockDim.x + threadIdx.x;
    if (i == 0){ g_count = 0; g_gen = 0; }

    if (i < NBLK * 32768){                 // W2 pack
        int blk = i >> 15, q = i & 32767;
        int reg = q & 1, lane = (q >> 1) & 31, u = q >> 6;
        int g = u & 3, tt = u >> 2;
        int n = blk*32 + g*8 + (lane >> 2);
        int k = tt*16 + (lane & 3)*2 + reg*8;
        g_W2p[i] = packbf(__float2bfloat16(W2[k*HH + n]),
                          __float2bfloat16(W2[(k+1)*HH + n]));
    }
    if (i < NBLK * 8192){                  // W1 pack
        int blk = i >> 13, q = i & 8191;
        int reg = q & 1, lane = (q >> 1) & 31, u = q >> 6;
        int g = u & 3, tt = u >> 2;
        int n = blk*32 + g*8 + (lane >> 2);
        int k = tt*16 + (lane & 3)*2 + reg*8;
        g_W1p[i] = packbf(__float2bfloat16(W1[k*HH + n]),
                          __float2bfloat16(W1[(k+1)*HH + n]));
    }
    if (i < 32 * 16384){                   // W3 pack
        int grp = i >> 14, q = i & 16383;
        int reg = q & 1, lane = (q >> 1) & 31, u = q >> 6;
        int wn = u & 1, tt = u >> 1;
        int n = grp*16 + wn*8 + (lane >> 2);
        int k = tt*16 + (lane & 3)*2 + reg*8;
        g_W3p[i] = packbf(__float2bfloat16(W3[k*CC + n]),
                          __float2bfloat16(W3[(k+1)*CC + n]));
    }
    if (i < BB * CC){                      // state init
        int b = i >> 9, c = i & (CC - 1);
        float v = x[b * TT * CC + c];
        g_y[i] = v;
        g_a[i] = __float2bfloat16(v);
        out[b * TT * CC + c] = v;
    }
}

// ---------------- launcher: 2 graph nodes ----------------
extern "C" void kernel_launch(void* const* d_in, const int* in_sizes, int n_in,
                              void* d_out, int out_size)
{
    const float* x  = (const float*)d_in[0];
    const float* W1 = (const float*)d_in[1];
    const float* b1 = (const float*)d_in[2];
    const float* W2 = (const float*)d_in[3];
    const float* b2 = (const float*)d_in[4];
    const float* W3 = (const float*)d_in[5];
    const float* b3 = (const float*)d_in[6];
    float* out = (float*)d_out;

    (void)in_sizes; (void)n_in; (void)out_size;

    cudaFuncSetAttribute(ode_kernel, cudaFuncAttributeMaxDynamicSharedMemorySize,
                         SMEM_BYTES);

    prep_kernel<<<(NBLK * 32768 + 255) / 256, 256>>>(x, W1, W2, W3, out);
    ode_kernel<<<NCTA, 256, SMEM_BYTES>>>(b1, b2, b3, out);
}

// round 10
// speedup vs baseline: 2.3805x; 1.1049x over previous
#include <cuda_runtime.h>
#include <cuda_bf16.h>
#include <stdint.h>

// Problem constants
#define BB 128
#define TT 256
#define CC 512
#define HH 2048
#define NCTA 256          /* persistent grid: 2 CTAs per SM region */
#define NBLK 64           /* weight N-block count (32-col blocks of H) */

__device__ __constant__ float k_DT      = (float)(1.0/765.0);
__device__ __constant__ float k_HALF_DT = (float)(0.5/765.0);
__device__ __constant__ float k_SIXTH   = (float)(1.0/(765.0*6.0));

// ---------------- device-global scratch (no runtime allocation) ----------------
// Weights pre-packed in mma.m16n8k16 B-fragment register order (see prep_kernel).
__device__ __align__(16) uint32_t g_W1p[NBLK * 8192];    // 64 blks x (512*32/2)
__device__ __align__(16) uint32_t g_W2p[NBLK * 32768];   // 64 blks x (2048*32/2)
__device__ __align__(16) uint32_t g_W3p[32 * 16384];     // 32 grps x (2048*16/2)

__device__ __align__(16) __nv_bfloat16 g_a [BB*CC];      // bf16 MLP input
__device__ __align__(16) __nv_bfloat16 g_h1[BB*HH];
__device__ __align__(16) __nv_bfloat16 g_h2[BB*HH];
__device__ float g_y [BB*CC];                            // fp32 ODE state
__device__ float g_ks[BB*CC];                            // fp32 RK4 k-sum

// ---------------- leaderless grid barrier (monotone counter) ----------------
__device__ unsigned g_count;

__device__ __forceinline__ void grid_barrier(unsigned &target){
    __syncthreads();
    if (threadIdx.x == 0){
        __threadfence();                         // release prior writes
        atomicAdd(&g_count, 1u);
        while (*((volatile unsigned*)&g_count) < target) { }
        __threadfence();                         // acquire
    }
    __syncthreads();
    target += gridDim.x;
}

// ---------------- PTX helpers ----------------
__device__ __forceinline__ void cp16(void* s, const void* g){
    uint32_t sa = (uint32_t)__cvta_generic_to_shared(s);
    asm volatile("cp.async.cg.shared.global [%0], [%1], 16;\n" :: "r"(sa), "l"(g));
}
__device__ __forceinline__ void cpcommit(){ asm volatile("cp.async.commit_group;\n"); }
template<int N> __device__ __forceinline__ void cpwait(){
    asm volatile("cp.async.wait_group %0;\n" :: "n"(N));
}
__device__ __forceinline__ void cpwait_dyn(int allow){
    if (allow >= 2)      cpwait<2>();
    else if (allow == 1) cpwait<1>();
    else                 cpwait<0>();
}

__device__ __forceinline__ void mma16816(float* c, const uint32_t* a, const uint32_t* b){
    asm volatile(
        "mma.sync.aligned.m16n8k16.row.col.f32.bf16.bf16.f32 "
        "{%0,%1,%2,%3},{%4,%5,%6,%7},{%8,%9},{%0,%1,%2,%3};\n"
        : "+f"(c[0]), "+f"(c[1]), "+f"(c[2]), "+f"(c[3])
        : "r"(a[0]), "r"(a[1]), "r"(a[2]), "r"(a[3]), "r"(b[0]), "r"(b[1]));
}

__device__ __forceinline__ void ldsm4(uint32_t* a, const __nv_bfloat16* p){
    uint32_t addr = (uint32_t)__cvta_generic_to_shared(p);
    asm volatile("ldmatrix.sync.aligned.m8n8.x4.shared.b16 {%0,%1,%2,%3},[%4];\n"
        : "=r"(a[0]), "=r"(a[1]), "=r"(a[2]), "=r"(a[3]) : "r"(addr));
}

__device__ __forceinline__ uint32_t packbf(__nv_bfloat16 lo, __nv_bfloat16 hi){
    union { __nv_bfloat162 v; uint32_t u; } t;
    t.v.x = lo; t.v.y = hi; return t.u;
}
__device__ __forceinline__ float fast_tanh(float x){
    float y; asm("tanh.approx.f32 %0, %1;" : "=f"(y) : "f"(x)); return y;
}

// ---------------- smem layout (dynamic, 104448 B per CTA; 2 CTAs/SM) --------
// L1/L2 view: As12 4 stages x [32][136] bf16 = 34816 B at 0
//             Bs12 4 stages x 2048 u32      = 32768 B at 34816
// L3 view:    As3  3 stages x [4q][16][136] = 52224 B at 0
//             Bs3  3 stages x 4096 u32      = 49152 B at 52224
//             Red  768 floats                =  3072 B at 101376
#define SMEM_BYTES 104448
#define DIST 3

// ---------------- layers 1 & 2: D = tanh(A @ W + b) -> bf16 ----------------
// Tile 32x32, warps 2(M)x4(N), MF=1, NF=1, KC=128.
template<int KDIM>
__device__ __forceinline__ void layer12(
    const __nv_bfloat16* __restrict__ Ag,   // pre-offset to tile row base
    const uint32_t* __restrict__ Bg,        // packed weight slice (N-block)
    __nv_bfloat16* __restrict__ As,
    uint32_t* __restrict__ Bs,
    __nv_bfloat16* __restrict__ Og,         // global out base (row 0)
    const float br[2],
    int tid, int lane, int wm, int wn, int g8, int t4, int mb, int nb)
{
    constexpr int NC = KDIM / 128;
    float acc[4] = {0.f, 0.f, 0.f, 0.f};

    auto loadChunk = [&](int c, int st){
        __nv_bfloat16* dst = As + st * 4352;
        const __nv_bfloat16* src = Ag + c * 128;
        #pragma unroll
        for (int i=0;i<2;i++){                  // 512 x 16B A tasks (32 rows)
            int task = i*256 + tid;
            int row = task >> 4, seg = task & 15;
            cp16(dst + row*136 + seg*8, src + row*KDIM + seg*8);
        }
        const uint32_t* bsrc = Bg + c * 2048;
        #pragma unroll
        for (int i=0;i<2;i++){                  // 512 x 16B B tasks
            int task = i*256 + tid;
            cp16(Bs + st*2048 + task*4, bsrc + task*4);
        }
    };

    #pragma unroll
    for (int d=0; d<DIST && d<NC; d++){ loadChunk(d, d); cpcommit(); }

    for (int c=0; c<NC; c++){
        cpwait_dyn(min(DIST-1, NC-1-c));
        __syncthreads();
        { int cn = c + DIST; if (cn < NC) loadChunk(cn, cn & 3); cpcommit(); }

        const __nv_bfloat16* Ast = As + (c & 3) * 4352;
        const uint32_t*      Bst = Bs + (c & 3) * 2048;
        #pragma unroll
        for (int ks=0; ks<8; ks++){
            uint32_t a[4];
            ldsm4(a, Ast + (wm*16 + (lane&15))*136 + ks*16 + (lane>>4)*8);
            uint2 bp = *reinterpret_cast<const uint2*>(
                Bst + ((ks*4 + wn)*32 + lane)*2);
            mma16816(acc, a, reinterpret_cast<const uint32_t*>(&bp));
        }
    }

    int r0 = mb + wm*16 + g8;
    int gc = nb + wn*8 + t4*2;
    union { __nv_bfloat162 v2; uint32_t u; } x0, x1;
    x0.v2.x = __float2bfloat16(fast_tanh(acc[0] + br[0]));
    x0.v2.y = __float2bfloat16(fast_tanh(acc[1] + br[1]));
    x1.v2.x = __float2bfloat16(fast_tanh(acc[2] + br[0]));
    x1.v2.y = __float2bfloat16(fast_tanh(acc[3] + br[1]));
    *reinterpret_cast<uint32_t*>(&Og[r0 * HH + gc])       = x0.u;
    *reinterpret_cast<uint32_t*>(&Og[(r0 + 8) * HH + gc]) = x1.u;
}

// ---------------- RK4 bookkeeping ----------------
__device__ __forceinline__ void rk_ep(int r, int c, float k, int stage, int out_t,
                                      float* __restrict__ out)
{
    int idx = r * CC + c;
    if (stage == 3){
        float total = g_ks[idx] + k;
        float yn = fmaf(k_SIXTH, total, g_y[idx]);
        g_y[idx] = yn;
        g_a[idx] = __float2bfloat16(yn);
        if (out_t >= 0) out[r * TT * CC + out_t * CC + c] = yn;
    } else {
        float ks = (stage == 0) ? k : fmaf(2.f, k, g_ks[idx]);
        g_ks[idx] = ks;
        float al = (stage == 2) ? k_DT : k_HALF_DT;
        g_a[idx] = __float2bfloat16(fmaf(al, k, g_y[idx]));
    }
}

// ---------------- layer 3: k = h2 @ W3 + b3, fused RK4 ----------------
// Tile 16x16, warps 2(N)x4(K-quarter), NC=4 chunks (each 4 x 128 of K).
__device__ __forceinline__ void layer3(
    const __nv_bfloat16* __restrict__ Ag,     // g_h2 + mb3*HH
    const uint32_t* __restrict__ Bg,          // packed W3 slice (16-col grp)
    __nv_bfloat16* __restrict__ As,
    uint32_t* __restrict__ Bs,
    float* __restrict__ Red,
    const float b3r[2],
    int s, int out_t, float* __restrict__ out,
    int tid, int lane, int wn3, int wk, int g8, int t4, int mb3, int nb3)
{
    constexpr int NC = 4;
    float acc[4] = {0.f, 0.f, 0.f, 0.f};

    auto loadChunk = [&](int c, int st){
        __nv_bfloat16* dst = As + st * 8704;
        #pragma unroll
        for (int i=0;i<4;i++){                  // 1024 A tasks: 4q x 16 rows x 16 segs
            int task = i*256 + tid;
            int q = task >> 8, rem = task & 255;
            int row = rem >> 4, seg = rem & 15;
            cp16(dst + q*2176 + row*136 + seg*8,
                 Ag + row*HH + q*512 + c*128 + seg*8);
        }
        #pragma unroll
        for (int i=0;i<4;i++){                  // 1024 B tasks: 4q x 1024 u32
            int task = i*256 + tid;
            int q = task >> 8, j = task & 255;
            cp16(Bs + st*4096 + q*1024 + j*4, Bg + q*4096 + c*1024 + j*4);
        }
    };

    #pragma unroll
    for (int d=0; d<2; d++){ loadChunk(d, d); cpcommit(); }

    for (int c=0; c<NC; c++){
        cpwait_dyn(min(1, NC-1-c));
        __syncthreads();
        { int cn = c + 2; if (cn < NC) loadChunk(cn, cn % 3); cpcommit(); }

        const __nv_bfloat16* Ast = As + (c % 3) * 8704 + wk*2176;
        const uint32_t*      Bst = Bs + (c % 3) * 4096 + wk*1024;
        #pragma unroll
        for (int ks=0; ks<8; ks++){
            uint32_t a[4];
            ldsm4(a, Ast + (lane&15)*136 + ks*16 + (lane>>4)*8);
            uint2 bp = *reinterpret_cast<const uint2*>(
                Bst + ((ks*2 + wn3)*32 + lane)*2);
            mma16816(acc, a, reinterpret_cast<const uint32_t*>(&bp));
        }
    }

    // 4-way split-K reduction: wk=1..3 publish, wk=0 adds + epilogue
    if (wk > 0){
        float* slot = Red + ((wk-1)*2 + wn3)*128 + lane*4;
        slot[0] = acc[0]; slot[1] = acc[1]; slot[2] = acc[2]; slot[3] = acc[3];
    }
    __syncthreads();
    if (wk == 0){
        #pragma unroll
        for (int j=0;j<3;j++){
            const float* slot = Red + (j*2 + wn3)*128 + lane*4;
            acc[0] += slot[0]; acc[1] += slot[1];
            acc[2] += slot[2]; acc[3] += slot[3];
        }
        int r0 = mb3 + g8;
        int gc = nb3 + wn3*8 + t4*2;
        rk_ep(r0,     gc,     acc[0] + b3r[0], s, out_t, out);
        rk_ep(r0,     gc + 1, acc[1] + b3r[1], s, out_t, out);
        rk_ep(r0 + 8, gc,     acc[2] + b3r[0], s, out_t, out);
        rk_ep(r0 + 8, gc + 1, acc[3] + b3r[1], s, out_t, out);
    }
}

// ---------------- persistent kernel ----------------
__global__ void __launch_bounds__(256, 2)
ode_kernel(const float* __restrict__ b1,
           const float* __restrict__ b2,
           const float* __restrict__ b3,
           float* __restrict__ out)
{
    extern __shared__ __align__(16) char smem[];
    __nv_bfloat16* As12 = reinterpret_cast<__nv_bfloat16*>(smem);
    uint32_t*      Bs12 = reinterpret_cast<uint32_t*>(smem + 34816);
    __nv_bfloat16* As3  = reinterpret_cast<__nv_bfloat16*>(smem);
    uint32_t*      Bs3  = reinterpret_cast<uint32_t*>(smem + 52224);
    float*         Red  = reinterpret_cast<float*>(smem + 101376);

    const int tid  = threadIdx.x;
    const int lane = tid & 31;
    const int warp = tid >> 5;
    const int wm   = warp & 1;            // L1/L2: M warp (2)
    const int wn   = warp >> 1;           // L1/L2: N warp (4)
    const int wn3  = warp & 1;            // L3: N warp (2)
    const int wk   = warp >> 1;           // L3: K-quarter warp (4)
    const int g8   = lane >> 2;
    const int t4   = lane & 3;
    const int cta  = blockIdx.x;
    const int mb   = (cta >> 6) * 32;     // L1/L2 row base (4 quarters)
    const int nb   = (cta & 63) * 32;     // L1/L2 column base
    const int mb3  = (cta >> 5) * 16;     // L3 row base (8 tiles)
    const int nb3  = (cta & 31) * 16;     // L3 column base

    // bias registers
    float b1r[2], b2r[2], b3r[2];
    { int c = nb + wn*8 + t4*2;  b1r[0] = b1[c]; b1r[1] = b1[c+1];
                                 b2r[0] = b2[c]; b2r[1] = b2[c+1]; }
    { int c = nb3 + wn3*8 + t4*2; b3r[0] = b3[c]; b3r[1] = b3[c+1]; }

    const uint32_t* W1g = g_W1p + (cta & 63) * 8192;
    const uint32_t* W2g = g_W2p + (cta & 63) * 32768;
    const uint32_t* W3g = g_W3p + (cta & 31) * 16384;
    unsigned target = gridDim.x;

    for (int t = 1; t < TT; t++){
        for (int sub = 0; sub < 3; sub++){
            for (int s = 0; s < 4; s++){
                layer12<CC>(g_a  + mb*CC, W1g, As12, Bs12, g_h1, b1r,
                            tid, lane, wm, wn, g8, t4, mb, nb);
                grid_barrier(target);
                layer12<HH>(g_h1 + mb*HH, W2g, As12, Bs12, g_h2, b2r,
                            tid, lane, wm, wn, g8, t4, mb, nb);
                grid_barrier(target);
                const int out_t = (s == 3 && sub == 2) ? t : -1;
                layer3(g_h2 + mb3*HH, W3g, As3, Bs3, Red, b3r, s, out_t, out,
                       tid, lane, wn3, wk, g8, t4, mb3, nb3);
                grid_barrier(target);
            }
        }
    }
}

// ---------------- prep: pack weights to fragment order, init state ----------------
__global__ void prep_kernel(const float* __restrict__ x,
                            const float* __restrict__ W1,
                            const float* __restrict__ W2,
                            const float* __restrict__ W3,
                            float* __restrict__ out)
{
    int i = blockIdx.x * blockDim.x + threadIdx.x;
    if (i == 0){ g_count = 0; }

    if (i < NBLK * 32768){                 // W2 pack
        int blk = i >> 15, q = i & 32767;
        int reg = q & 1, lane = (q >> 1) & 31, u = q >> 6;
        int g = u & 3, tt = u >> 2;
        int n = blk*32 + g*8 + (lane >> 2);
        int k = tt*16 + (lane & 3)*2 + reg*8;
        g_W2p[i] = packbf(__float2bfloat16(W2[k*HH + n]),
                          __float2bfloat16(W2[(k+1)*HH + n]));
    }
    if (i < NBLK * 8192){                  // W1 pack
        int blk = i >> 13, q = i & 8191;
        int reg = q & 1, lane = (q >> 1) & 31, u = q >> 6;
        int g = u & 3, tt = u >> 2;
        int n = blk*32 + g*8 + (lane >> 2);
        int k = tt*16 + (lane & 3)*2 + reg*8;
        g_W1p[i] = packbf(__float2bfloat16(W1[k*HH + n]),
                          __float2bfloat16(W1[(k+1)*HH + n]));
    }
    if (i < 32 * 16384){                   // W3 pack
        int grp = i >> 14, q = i & 16383;
        int reg = q & 1, lane = (q >> 1) & 31, u = q >> 6;
        int wn = u & 1, tt = u >> 1;
        int n = grp*16 + wn*8 + (lane >> 2);
        int k = tt*16 + (lane & 3)*2 + reg*8;
        g_W3p[i] = packbf(__float2bfloat16(W3[k*CC + n]),
                          __float2bfloat16(W3[(k+1)*CC + n]));
    }
    if (i < BB * CC){                      // state init
        int b = i >> 9, c = i & (CC - 1);
        float v = x[b * TT * CC + c];
        g_y[i] = v;
        g_a[i] = __float2bfloat16(v);
        out[b * TT * CC + c] = v;
    }
}

// ---------------- launcher: 2 graph nodes ----------------
extern "C" void kernel_launch(void* const* d_in, const int* in_sizes, int n_in,
                              void* d_out, int out_size)
{
    const float* x  = (const float*)d_in[0];
    const float* W1 = (const float*)d_in[1];
    const float* b1 = (const float*)d_in[2];
    const float* W2 = (const float*)d_in[3];
    const float* b2 = (const float*)d_in[4];
    const float* W3 = (const float*)d_in[5];
    const float* b3 = (const float*)d_in[6];
    float* out = (float*)d_out;

    (void)in_sizes; (void)n_in; (void)out_size;

    cudaFuncSetAttribute(ode_kernel, cudaFuncAttributeMaxDynamicSharedMemorySize,
                         SMEM_BYTES);

    prep_kernel<<<(NBLK * 32768 + 255) / 256, 256>>>(x, W1, W2, W3, out);
    ode_kernel<<<NCTA, 256, SMEM_BYTES>>>(b1, b2, b3, out);
}